// round 14
// baseline (speedup 1.0000x reference)
#include <cuda_runtime.h>
#include <cuda_bf16.h>
#include <cstddef>

// Problem constants
#define B 32
#define N 2048
#define D 1024
#define H 16
#define HD 64
#define SCALE 0.125f   // 1/sqrt(64)
#define NSPLIT 8

// ---------------- scratch (device globals; no allocation allowed) -----------
__device__ float g_q[D];
__device__ float g_u[H * D];                 // u[h,i] pre-scaled
__device__ float g_c[H];
__device__ int   g_force[B];
__device__ unsigned char g_maskb[B * N];
__device__ float g_scores[B * H * N];        // raw masked scores
__device__ float g_pm[B * H * 16];           // per-128-row-tile max
__device__ float g_pz[B * H * 16];           // per-tile sumexp (rel. tile max)
__device__ float g_ctxp[NSPLIT * B * H * D]; // partial ctx per n-split (16 MB)
__device__ float g_pooled[B * D];

typedef unsigned long long ull;

__device__ __forceinline__ float warp_sum(float v) {
    #pragma unroll
    for (int o = 16; o; o >>= 1) v += __shfl_xor_sync(0xffffffffu, v, o);
    return v;
}
__device__ __forceinline__ ull f2fma(ull a, ull b, ull c) {
    ull d; asm("fma.rn.f32x2 %0, %1, %2, %3;" : "=l"(d) : "l"(a), "l"(b), "l"(c)); return d;
}
__device__ __forceinline__ ull f2add(ull a, ull b) {
    ull d; asm("add.rn.f32x2 %0, %1, %2;" : "=l"(d) : "l"(a), "l"(b)); return d;
}
__device__ __forceinline__ ull pack2(float lo, float hi) {
    ull r; asm("mov.b64 %0, {%1, %2};" : "=l"(r) : "f"(lo), "f"(hi)); return r;
}
__device__ __forceinline__ float2 unpack2(ull v) {
    float2 r; asm("mov.b64 {%0, %1}, %2;" : "=f"(r.x), "=f"(r.y) : "l"(v)); return r;
}

// ---------------- KA: fused q-projection + mask canonicalization ------------
// blocks 0..127: q[j] = query . w_q[j,:] + b_q[j]   (one warp per j)
// blocks 128..159: batch b = blk-128: detect mask wire dtype (redundant,
// deterministic, L2-served), canonicalize to g_maskb, compute g_force[b].
__global__ void kA(const float* __restrict__ query, const float* __restrict__ w_q,
                   const float* __restrict__ b_q, const void* __restrict__ mraw) {
    if (blockIdx.x < 128) {
        int j    = (blockIdx.x * 256 + threadIdx.x) >> 5;
        int lane = threadIdx.x & 31;
        float acc = 0.f;
        const float* wr = w_q + (size_t)j * D;
        for (int i = lane; i < D; i += 32) acc = fmaf(query[i], wr[i], acc);
        acc = warp_sum(acc);
        if (lane == 0) g_q[j] = acc + b_q[j];
        return;
    }
    // ---- mask part ----
    int b = blockIdx.x - 128;
    const unsigned int*   wrd = (const unsigned int*)mraw;
    const unsigned short* hlf = (const unsigned short*)mraw;
    const unsigned char*  byt = (const unsigned char*)mraw;

    __shared__ int s_bf, s_bb, s_bi, s_found[8];
    int t = threadIdx.x;
    if (t == 0) { s_bf = 0; s_bb = 0; s_bi = 0; }
    __syncthreads();

    int bf = 0, bb = 0, bi = 0;
    for (int i = t; i < (B * N) / 4; i += 256) {   // 16384 words, in-bounds all dtypes
        unsigned int x = wrd[i];
        if (x != 0u && x != 0x3F800000u) bf = 1;
        unsigned int lo = x & 0xFFFFu, hi = x >> 16;
        if ((lo != 0u && lo != 0x3F80u) || (hi != 0u && hi != 0x3F80u)) bb = 1;
        if (x > 1u) bi = 1;
    }
    if (bf) s_bf = 1;
    if (bb) s_bb = 1;
    if (bi) s_bi = 1;
    __syncthreads();
    int mode = !s_bf ? 0 : (!s_bb ? 1 : (!s_bi ? 2 : 3));

    int found = 0;
    for (int e = t; e < N; e += 256) {
        int idx = b * N + e;
        unsigned char v;
        if      (mode == 0) v = (wrd[idx] != 0u);   // float32
        else if (mode == 1) v = (hlf[idx] != 0);    // bf16
        else if (mode == 2) v = (wrd[idx] != 0u);   // int32
        else                v = (byt[idx] != 0);    // bool bytes
        g_maskb[idx] = v;
        found |= v;
    }
    int w = t >> 5, lane = t & 31;
    found = __ballot_sync(0xffffffffu, found);
    if (lane == 0) s_found[w] = found;
    __syncthreads();
    if (t == 0) {
        int any = 0;
        #pragma unroll
        for (int i = 0; i < 8; i++) any |= s_found[i];
        g_force[b] = (any == 0);
    }
}

// ---------------- KB: fused u[h,i] + c[h] ------------------------------------
__global__ void kB(const float* __restrict__ w_k, const float* __restrict__ b_k) {
    if (blockIdx.x < 64) {
        int t = blockIdx.x * 256 + threadIdx.x;
        int h = t >> 10;
        int i = t & (D - 1);
        float acc = 0.f;
        #pragma unroll 8
        for (int j = 0; j < HD; j++)
            acc = fmaf(g_q[h * HD + j], w_k[(size_t)(h * HD + j) * D + i], acc);
        g_u[t] = acc * SCALE;
        return;
    }
    // c[h] = scale * q_h . b_k_h  (16-lane groups)
    int t = threadIdx.x;
    int h = t >> 4, l = t & 15;
    float acc = 0.f;
    #pragma unroll
    for (int k = 0; k < 4; k++)
        acc = fmaf(g_q[h * HD + l + 16 * k], b_k[h * HD + l + 16 * k], acc);
    #pragma unroll
    for (int o = 1; o <= 8; o <<= 1) acc += __shfl_xor_sync(0xffffffffu, acc, o, 16);
    if (l == 0) g_c[h] = acc * SCALE;
}

// ---------------- K3: scores + per-tile softmax partials ---------------------
// thread = (rg, s): rows rg*4..+3, i-slice {c*32 + s*4 ..+3}; ALL 8 head-pairs
// in f32x2 registers. z: direct coalesced gmem LDG.128 (MLP=4x2). u: smem
// stride-18 pairs, one read amortized over 4 rows. i-partials reduced across
// the 8 s-lanes via 3x shfl.xor. Tail: per-(h, tile) max & sumexp partials.
__global__ void __launch_bounds__(256, 2) k_scores(const float* __restrict__ z) {
    extern __shared__ float us[];   // [1024][18] floats, then pm[16][32], pz[16][32]
    float* pmS = us + 1024 * 18;
    float* pzS = pmS + 16 * 32;
    for (int idx = threadIdx.x; idx < H * D; idx += 256) {
        int h = idx >> 10, i = idx & (D - 1);
        us[i * 18 + h] = g_u[idx];
    }
    __syncthreads();

    int s    = threadIdx.x & 7;
    int rg   = threadIdx.x >> 3;               // 0..31
    int row0 = blockIdx.x * 128 + rg * 4;
    int b    = blockIdx.x >> 4;
    int nblk = blockIdx.x & 15;
    const float* zbase = z + (size_t)row0 * D;

    ull acc[4][8];
    #pragma unroll
    for (int r = 0; r < 4; r++)
        #pragma unroll
        for (int hp = 0; hp < 8; hp++) acc[r][hp] = 0ull;

    #pragma unroll 2
    for (int c = 0; c < 32; c++) {
        int ib = c * 32 + s * 4;
        float za[4][4];
        #pragma unroll
        for (int r = 0; r < 4; r++)
            *reinterpret_cast<float4*>(za[r]) =
                __ldg(reinterpret_cast<const float4*>(zbase + (size_t)r * D + ib));
        #pragma unroll
        for (int ii = 0; ii < 4; ii++) {
            const ull* urow = reinterpret_cast<const ull*>(us + (size_t)(ib + ii) * 18);
            ull zz[4];
            #pragma unroll
            for (int r = 0; r < 4; r++) zz[r] = pack2(za[r][ii], za[r][ii]);
            #pragma unroll
            for (int hp = 0; hp < 8; hp++) {
                ull uv = urow[hp];
                #pragma unroll
                for (int r = 0; r < 4; r++)
                    acc[r][hp] = f2fma(zz[r], uv, acc[r][hp]);
            }
        }
    }

    // reduce over the 8 s-lanes
    #pragma unroll
    for (int r = 0; r < 4; r++)
        #pragma unroll
        for (int hp = 0; hp < 8; hp++) {
            ull v = acc[r][hp];
            #pragma unroll
            for (int o = 1; o <= 4; o <<= 1)
                v = f2add(v, __shfl_xor_sync(0xffffffffu, v, o));
            acc[r][hp] = v;
        }

    float neg_inf = __int_as_float(0xff800000);
    int   force   = g_force[b];
    float sv0[4], sv1[4];
    #pragma unroll
    for (int hp = 0; hp < 8; hp++) if (hp == s) {
        float ch0 = g_c[2 * hp], ch1 = g_c[2 * hp + 1];
        #pragma unroll
        for (int r = 0; r < 4; r++) {
            int n = (row0 + r) & (N - 1);
            bool valid = (g_maskb[b * N + n] != 0) || (n == 0 && force);
            float2 v = unpack2(acc[r][hp]);
            float s0 = valid ? v.x + ch0 : neg_inf;
            float s1 = valid ? v.y + ch1 : neg_inf;
            g_scores[((size_t)(b * H + 2 * hp)) * N + n]     = s0;
            g_scores[((size_t)(b * H + 2 * hp + 1)) * N + n] = s1;
            sv0[r] = s0; sv1[r] = s1;
        }
    }

    // per-thread (4-row) max & sumexp for heads 2s, 2s+1
    float m0 = neg_inf, m1 = neg_inf;
    #pragma unroll
    for (int r = 0; r < 4; r++) { m0 = fmaxf(m0, sv0[r]); m1 = fmaxf(m1, sv1[r]); }
    float z0 = 0.f, z1 = 0.f;
    if (m0 != neg_inf) {
        #pragma unroll
        for (int r = 0; r < 4; r++) z0 += __expf(sv0[r] - m0);
    }
    if (m1 != neg_inf) {
        #pragma unroll
        for (int r = 0; r < 4; r++) z1 += __expf(sv1[r] - m1);
    }
    pmS[(2 * s) * 32 + rg] = m0;     pzS[(2 * s) * 32 + rg] = z0;
    pmS[(2 * s + 1) * 32 + rg] = m1; pzS[(2 * s + 1) * 32 + rg] = z1;
    __syncthreads();

    // block combine: thread h (<16) reduces 32 rg partials
    if (threadIdx.x < 16) {
        int h = threadIdx.x;
        float M = neg_inf;
        #pragma unroll 8
        for (int i = 0; i < 32; i++) M = fmaxf(M, pmS[h * 32 + i]);
        float Z = 0.f;
        if (M != neg_inf) {
            #pragma unroll 8
            for (int i = 0; i < 32; i++)
                Z += pzS[h * 32 + i] * __expf(pmS[h * 32 + i] - M);
        }
        g_pm[((size_t)(b * H + h)) * 16 + nblk] = M;
        g_pz[((size_t)(b * H + h)) * 16 + nblk] = Z;
    }
}

// ---------------- K5: ctx partial over an n-split, softmax finalized inline --
// block = (b, ns): 256 n rows (NSPLIT=8 -> grid 256, ~1.7 blocks/SM, 2 co-
// resident thanks to 18.5KB smem). Combine the 16 tile partials -> (M, 1/Z)
// per h, stage p = exp(s-M)/Z into smem, then the FMA2 main loop with a
// +1-deep z prefetch (index clamped at N-1: never reads past z).
__global__ void __launch_bounds__(256) k_ctx(const float* __restrict__ z) {
    __shared__ __align__(16) float ps[256 * 18];
    __shared__ float sM[16], sI[16];
    int b  = blockIdx.x >> 3;
    int ns = blockIdx.x & 7;
    int n0 = ns * (N / NSPLIT);            // 256 rows of n
    int i0 = threadIdx.x * 4;
    float neg_inf = __int_as_float(0xff800000);

    if (threadIdx.x < 16) {
        int h = threadIdx.x;
        const float* pm = g_pm + ((size_t)(b * H + h)) * 16;
        const float* pz = g_pz + ((size_t)(b * H + h)) * 16;
        float M = neg_inf;
        #pragma unroll
        for (int i = 0; i < 16; i++) M = fmaxf(M, pm[i]);
        float Z = 0.f;
        #pragma unroll
        for (int i = 0; i < 16; i++) Z += pz[i] * __expf(pm[i] - M);
        sM[h] = M;
        sI[h] = 1.f / Z;
    }
    __syncthreads();

    for (int idx = threadIdx.x; idx < 256 * H; idx += 256) {
        int h = idx >> 8, nc = idx & 255;
        float sc = g_scores[((size_t)(b * H + h)) * N + n0 + nc];
        ps[nc * 18 + h] = __expf(sc - sM[h]) * sI[h];
    }
    __syncthreads();

    const float* zb = z + (size_t)b * N * D;

    ull acc[4][8];
    #pragma unroll
    for (int ii = 0; ii < 4; ii++)
        #pragma unroll
        for (int hp = 0; hp < 8; hp++) acc[ii][hp] = 0ull;

    float4 nxt = __ldg(reinterpret_cast<const float4*>(zb + (size_t)n0 * D + i0));
    #pragma unroll 2
    for (int nc = 0; nc < 256; nc++) {
        float za[4];
        *reinterpret_cast<float4*>(za) = nxt;
        int npre = n0 + nc + 1;
        if (npre > N - 1) npre = N - 1;          // clamp: stay inside z
        nxt = __ldg(reinterpret_cast<const float4*>(zb + (size_t)npre * D + i0));
        ull zz[4];
        #pragma unroll
        for (int ii = 0; ii < 4; ii++) zz[ii] = pack2(za[ii], za[ii]);
        const ull* pp = reinterpret_cast<const ull*>(ps + nc * 18);
        #pragma unroll
        for (int hp = 0; hp < 8; hp++) {
            ull pv = pp[hp];
            #pragma unroll
            for (int ii = 0; ii < 4; ii++)
                acc[ii][hp] = f2fma(pv, zz[ii], acc[ii][hp]);
        }
    }

    float* dst = g_ctxp + (size_t)ns * (B * H * D) + (size_t)b * H * D;
    #pragma unroll
    for (int hp = 0; hp < 8; hp++)
        #pragma unroll
        for (int ii = 0; ii < 4; ii++) {
            float2 v = unpack2(acc[ii][hp]);
            dst[(size_t)(2 * hp) * D + i0 + ii]     = v.x;
            dst[(size_t)(2 * hp + 1) * D + i0 + ii] = v.y;
        }
}

// ---------------- K6: pooled = w_v . (sum of 8 ctx partials) + b_v -----------
#define SLAB4 (B * H * D / 4)
__global__ void k_pooled(const float* __restrict__ w_v, const float* __restrict__ b_v) {
    __shared__ float ws[8 * D];
    int j0 = blockIdx.x * 8;
    for (int idx = threadIdx.x; idx < 8 * D; idx += 256)
        ws[idx] = w_v[(size_t)j0 * D + idx];
    __syncthreads();

    int w = threadIdx.x >> 5, lane = threadIdx.x & 31;
    int j = j0 + w;
    int h = j >> 6;
    float bias = b_v[j];
    const float4* wr = reinterpret_cast<const float4*>(ws + w * D);
    for (int b = 0; b < B; b++) {
        const float4* cx = reinterpret_cast<const float4*>(g_ctxp) +
                           ((size_t)(b * H + h)) * (D / 4);
        float acc = 0.f;
        #pragma unroll
        for (int i4 = lane; i4 < D / 4; i4 += 32) {
            float4 a = wr[i4];
            float cxs = 0.f, cys = 0.f, czs = 0.f, cws = 0.f;
            #pragma unroll
            for (int ns = 0; ns < NSPLIT; ns++) {
                float4 c = __ldg(&cx[(size_t)ns * SLAB4 + i4]);
                cxs += c.x; cys += c.y; czs += c.z; cws += c.w;
            }
            acc = fmaf(a.x, cxs, acc);
            acc = fmaf(a.y, cys, acc);
            acc = fmaf(a.z, czs, acc);
            acc = fmaf(a.w, cws, acc);
        }
        acc = warp_sum(acc);
        if (lane == 0) g_pooled[b * D + j] = acc + bias;
    }
}

// ---------------- K7: out[b,j] = w_o[j,:] . pooled[b,:] + b_o[j] -------------
__global__ void k_out(const float* __restrict__ w_o, const float* __restrict__ b_o,
                      float* __restrict__ out) {
    __shared__ float ws[8 * D];
    int j0 = blockIdx.x * 8;
    for (int idx = threadIdx.x; idx < 8 * D; idx += 256)
        ws[idx] = w_o[(size_t)j0 * D + idx];
    __syncthreads();

    int w = threadIdx.x >> 5, lane = threadIdx.x & 31;
    int j = j0 + w;
    float bias = b_o[j];
    const float4* wr = reinterpret_cast<const float4*>(ws + w * D);
    for (int b = 0; b < B; b++) {
        const float4* px = reinterpret_cast<const float4*>(g_pooled + (size_t)b * D);
        float acc = 0.f;
        #pragma unroll
        for (int i4 = lane; i4 < D / 4; i4 += 32) {
            float4 a = wr[i4];
            float4 c = __ldg(&px[i4]);
            acc = fmaf(a.x, c.x, acc);
            acc = fmaf(a.y, c.y, acc);
            acc = fmaf(a.z, c.z, acc);
            acc = fmaf(a.w, c.w, acc);
        }
        acc = warp_sum(acc);
        if (lane == 0) out[b * D + j] = acc + bias;
    }
}

// ---------------- launch ------------------------------------------------------
extern "C" void kernel_launch(void* const* d_in, const int* in_sizes, int n_in,
                              void* d_out, int out_size) {
    const float* z     = (const float*)d_in[0];
    const void*  mask  = d_in[1];
    const float* query = (const float*)d_in[2];
    const float* w_q   = (const float*)d_in[3];
    const float* w_k   = (const float*)d_in[4];
    const float* w_v   = (const float*)d_in[5];
    const float* b_q   = (const float*)d_in[6];
    const float* b_k   = (const float*)d_in[7];
    const float* b_v   = (const float*)d_in[8];
    const float* w_o   = (const float*)d_in[9];
    const float* b_o   = (const float*)d_in[10];
    float*       out   = (float*)d_out;

    // u smem (1024*18) + softmax partials (2*16*32) = 77824 B
    cudaFuncSetAttribute(k_scores, cudaFuncAttributeMaxDynamicSharedMemorySize, 77824);

    kA       <<<160, 256>>>(query, w_q, b_q, mask);
    kB       <<<65, 256>>>(w_k, b_k);
    k_scores <<<(B * N) / 128, 256, 77824>>>(z);
    k_ctx    <<<B * NSPLIT, 256>>>(z);
    k_pooled <<<D / 8, 256>>>(w_v, b_v);
    k_out    <<<D / 8, 256>>>(w_o, b_o, out);
}

// round 15
// speedup vs baseline: 1.8768x; 1.8768x over previous
#include <cuda_runtime.h>
#include <cuda_bf16.h>
#include <cstddef>

// Problem constants
#define B 32
#define N 2048
#define D 1024
#define H 16
#define HD 64
#define SCALE 0.125f   // 1/sqrt(64)
#define NSPLIT 8

// ---------------- scratch (device globals; no allocation allowed) -----------
__device__ float g_q[D];
__device__ float g_u[H * D];                 // u[h,i] pre-scaled
__device__ float g_c[H];
__device__ int   g_force[B];
__device__ unsigned char g_maskb[B * N];
__device__ float g_scores[B * H * N];        // raw masked scores
__device__ float g_pm[B * H * 16];           // per-128-row-tile max
__device__ float g_pz[B * H * 16];           // per-tile sumexp (rel. tile max)
__device__ float g_ctxp[NSPLIT * B * H * D]; // partial ctx per n-split (16 MB)
__device__ float g_ctx[B * H * D];           // reduced ctx (2 MB)
__device__ float g_pooled[B * D];

typedef unsigned long long ull;

__device__ __forceinline__ float warp_sum(float v) {
    #pragma unroll
    for (int o = 16; o; o >>= 1) v += __shfl_xor_sync(0xffffffffu, v, o);
    return v;
}
__device__ __forceinline__ ull f2fma(ull a, ull b, ull c) {
    ull d; asm("fma.rn.f32x2 %0, %1, %2, %3;" : "=l"(d) : "l"(a), "l"(b), "l"(c)); return d;
}
__device__ __forceinline__ ull f2add(ull a, ull b) {
    ull d; asm("add.rn.f32x2 %0, %1, %2;" : "=l"(d) : "l"(a), "l"(b)); return d;
}
__device__ __forceinline__ ull pack2(float lo, float hi) {
    ull r; asm("mov.b64 %0, {%1, %2};" : "=l"(r) : "f"(lo), "f"(hi)); return r;
}
__device__ __forceinline__ float2 unpack2(ull v) {
    float2 r; asm("mov.b64 {%0, %1}, %2;" : "=f"(r.x), "=f"(r.y) : "l"(v)); return r;
}

// ---------------- KA: fused q-projection + mask canonicalization ------------
__global__ void kA(const float* __restrict__ query, const float* __restrict__ w_q,
                   const float* __restrict__ b_q, const void* __restrict__ mraw) {
    if (blockIdx.x < 128) {
        int j    = (blockIdx.x * 256 + threadIdx.x) >> 5;
        int lane = threadIdx.x & 31;
        float acc = 0.f;
        const float* wr = w_q + (size_t)j * D;
        for (int i = lane; i < D; i += 32) acc = fmaf(query[i], wr[i], acc);
        acc = warp_sum(acc);
        if (lane == 0) g_q[j] = acc + b_q[j];
        return;
    }
    // ---- mask part: batch b, redundant deterministic dtype detection ----
    int b = blockIdx.x - 128;
    const unsigned int*   wrd = (const unsigned int*)mraw;
    const unsigned short* hlf = (const unsigned short*)mraw;
    const unsigned char*  byt = (const unsigned char*)mraw;

    __shared__ int s_bf, s_bb, s_bi, s_found[8];
    int t = threadIdx.x;
    if (t == 0) { s_bf = 0; s_bb = 0; s_bi = 0; }
    __syncthreads();

    int bf = 0, bb = 0, bi = 0;
    for (int i = t; i < (B * N) / 4; i += 256) {   // 16384 words, in-bounds all dtypes
        unsigned int x = wrd[i];
        if (x != 0u && x != 0x3F800000u) bf = 1;
        unsigned int lo = x & 0xFFFFu, hi = x >> 16;
        if ((lo != 0u && lo != 0x3F80u) || (hi != 0u && hi != 0x3F80u)) bb = 1;
        if (x > 1u) bi = 1;
    }
    if (bf) s_bf = 1;
    if (bb) s_bb = 1;
    if (bi) s_bi = 1;
    __syncthreads();
    int mode = !s_bf ? 0 : (!s_bb ? 1 : (!s_bi ? 2 : 3));

    int found = 0;
    for (int e = t; e < N; e += 256) {
        int idx = b * N + e;
        unsigned char v;
        if      (mode == 0) v = (wrd[idx] != 0u);   // float32
        else if (mode == 1) v = (hlf[idx] != 0);    // bf16
        else if (mode == 2) v = (wrd[idx] != 0u);   // int32
        else                v = (byt[idx] != 0);    // bool bytes
        g_maskb[idx] = v;
        found |= v;
    }
    int w = t >> 5, lane = t & 31;
    found = __ballot_sync(0xffffffffu, found);
    if (lane == 0) s_found[w] = found;
    __syncthreads();
    if (t == 0) {
        int any = 0;
        #pragma unroll
        for (int i = 0; i < 8; i++) any |= s_found[i];
        g_force[b] = (any == 0);
    }
}

// ---------------- KB: fused u[h,i] + c[h] ------------------------------------
__global__ void kB(const float* __restrict__ w_k, const float* __restrict__ b_k) {
    if (blockIdx.x < 64) {
        int t = blockIdx.x * 256 + threadIdx.x;
        int h = t >> 10;
        int i = t & (D - 1);
        float acc = 0.f;
        #pragma unroll 8
        for (int j = 0; j < HD; j++)
            acc = fmaf(g_q[h * HD + j], w_k[(size_t)(h * HD + j) * D + i], acc);
        g_u[t] = acc * SCALE;
        return;
    }
    int t = threadIdx.x;
    int h = t >> 4, l = t & 15;
    float acc = 0.f;
    #pragma unroll
    for (int k = 0; k < 4; k++)
        acc = fmaf(g_q[h * HD + l + 16 * k], b_k[h * HD + l + 16 * k], acc);
    #pragma unroll
    for (int o = 1; o <= 8; o <<= 1) acc += __shfl_xor_sync(0xffffffffu, acc, o, 16);
    if (l == 0) g_c[h] = acc * SCALE;
}

// ---------------- K3: scores + per-tile softmax partials ---------------------
__global__ void __launch_bounds__(256, 2) k_scores(const float* __restrict__ z) {
    extern __shared__ float us[];   // [1024][18] floats, then pm[16][32], pz[16][32]
    float* pmS = us + 1024 * 18;
    float* pzS = pmS + 16 * 32;
    for (int idx = threadIdx.x; idx < H * D; idx += 256) {
        int h = idx >> 10, i = idx & (D - 1);
        us[i * 18 + h] = g_u[idx];
    }
    __syncthreads();

    int s    = threadIdx.x & 7;
    int rg   = threadIdx.x >> 3;               // 0..31
    int row0 = blockIdx.x * 128 + rg * 4;
    int b    = blockIdx.x >> 4;
    int nblk = blockIdx.x & 15;
    const float* zbase = z + (size_t)row0 * D;

    ull acc[4][8];
    #pragma unroll
    for (int r = 0; r < 4; r++)
        #pragma unroll
        for (int hp = 0; hp < 8; hp++) acc[r][hp] = 0ull;

    #pragma unroll 2
    for (int c = 0; c < 32; c++) {
        int ib = c * 32 + s * 4;
        float za[4][4];
        #pragma unroll
        for (int r = 0; r < 4; r++)
            *reinterpret_cast<float4*>(za[r]) =
                __ldg(reinterpret_cast<const float4*>(zbase + (size_t)r * D + ib));
        #pragma unroll
        for (int ii = 0; ii < 4; ii++) {
            const ull* urow = reinterpret_cast<const ull*>(us + (size_t)(ib + ii) * 18);
            ull zz[4];
            #pragma unroll
            for (int r = 0; r < 4; r++) zz[r] = pack2(za[r][ii], za[r][ii]);
            #pragma unroll
            for (int hp = 0; hp < 8; hp++) {
                ull uv = urow[hp];
                #pragma unroll
                for (int r = 0; r < 4; r++)
                    acc[r][hp] = f2fma(zz[r], uv, acc[r][hp]);
            }
        }
    }

    #pragma unroll
    for (int r = 0; r < 4; r++)
        #pragma unroll
        for (int hp = 0; hp < 8; hp++) {
            ull v = acc[r][hp];
            #pragma unroll
            for (int o = 1; o <= 4; o <<= 1)
                v = f2add(v, __shfl_xor_sync(0xffffffffu, v, o));
            acc[r][hp] = v;
        }

    float neg_inf = __int_as_float(0xff800000);
    int   force   = g_force[b];
    float sv0[4], sv1[4];
    #pragma unroll
    for (int hp = 0; hp < 8; hp++) if (hp == s) {
        float ch0 = g_c[2 * hp], ch1 = g_c[2 * hp + 1];
        #pragma unroll
        for (int r = 0; r < 4; r++) {
            int n = (row0 + r) & (N - 1);
            bool valid = (g_maskb[b * N + n] != 0) || (n == 0 && force);
            float2 v = unpack2(acc[r][hp]);
            float s0 = valid ? v.x + ch0 : neg_inf;
            float s1 = valid ? v.y + ch1 : neg_inf;
            g_scores[((size_t)(b * H + 2 * hp)) * N + n]     = s0;
            g_scores[((size_t)(b * H + 2 * hp + 1)) * N + n] = s1;
            sv0[r] = s0; sv1[r] = s1;
        }
    }

    float m0 = neg_inf, m1 = neg_inf;
    #pragma unroll
    for (int r = 0; r < 4; r++) { m0 = fmaxf(m0, sv0[r]); m1 = fmaxf(m1, sv1[r]); }
    float z0 = 0.f, z1 = 0.f;
    if (m0 != neg_inf) {
        #pragma unroll
        for (int r = 0; r < 4; r++) z0 += __expf(sv0[r] - m0);
    }
    if (m1 != neg_inf) {
        #pragma unroll
        for (int r = 0; r < 4; r++) z1 += __expf(sv1[r] - m1);
    }
    pmS[(2 * s) * 32 + rg] = m0;     pzS[(2 * s) * 32 + rg] = z0;
    pmS[(2 * s + 1) * 32 + rg] = m1; pzS[(2 * s + 1) * 32 + rg] = z1;
    __syncthreads();

    if (threadIdx.x < 16) {
        int h = threadIdx.x;
        float M = neg_inf;
        #pragma unroll 8
        for (int i = 0; i < 32; i++) M = fmaxf(M, pmS[h * 32 + i]);
        float Z = 0.f;
        if (M != neg_inf) {
            #pragma unroll 8
            for (int i = 0; i < 32; i++)
                Z += pzS[h * 32 + i] * __expf(pmS[h * 32 + i] - M);
        }
        g_pm[((size_t)(b * H + h)) * 16 + nblk] = M;
        g_pz[((size_t)(b * H + h)) * 16 + nblk] = Z;
    }
}

// ---------------- K5: ctx partial over an n-split, softmax finalized inline --
__global__ void __launch_bounds__(256) k_ctx(const float* __restrict__ z) {
    __shared__ __align__(16) float ps[256 * 18];
    __shared__ float sM[16], sI[16];
    int b  = blockIdx.x >> 3;
    int ns = blockIdx.x & 7;
    int n0 = ns * (N / NSPLIT);            // 256 rows of n
    int i0 = threadIdx.x * 4;
    float neg_inf = __int_as_float(0xff800000);

    if (threadIdx.x < 16) {
        int h = threadIdx.x;
        const float* pm = g_pm + ((size_t)(b * H + h)) * 16;
        const float* pz = g_pz + ((size_t)(b * H + h)) * 16;
        float M = neg_inf;
        #pragma unroll
        for (int i = 0; i < 16; i++) M = fmaxf(M, pm[i]);
        float Z = 0.f;
        #pragma unroll
        for (int i = 0; i < 16; i++) Z += pz[i] * __expf(pm[i] - M);
        sM[h] = M;
        sI[h] = 1.f / Z;
    }
    __syncthreads();

    for (int idx = threadIdx.x; idx < 256 * H; idx += 256) {
        int h = idx >> 8, nc = idx & 255;
        float sc = g_scores[((size_t)(b * H + h)) * N + n0 + nc];
        ps[nc * 18 + h] = __expf(sc - sM[h]) * sI[h];
    }
    __syncthreads();

    const float* zb = z + (size_t)b * N * D;

    ull acc[4][8];
    #pragma unroll
    for (int ii = 0; ii < 4; ii++)
        #pragma unroll
        for (int hp = 0; hp < 8; hp++) acc[ii][hp] = 0ull;

    float4 nxt = __ldg(reinterpret_cast<const float4*>(zb + (size_t)n0 * D + i0));
    #pragma unroll 2
    for (int nc = 0; nc < 256; nc++) {
        float za[4];
        *reinterpret_cast<float4*>(za) = nxt;
        int npre = n0 + nc + 1;
        if (npre > N - 1) npre = N - 1;          // clamp: stay inside z
        nxt = __ldg(reinterpret_cast<const float4*>(zb + (size_t)npre * D + i0));
        ull zz[4];
        #pragma unroll
        for (int ii = 0; ii < 4; ii++) zz[ii] = pack2(za[ii], za[ii]);
        const ull* pp = reinterpret_cast<const ull*>(ps + nc * 18);
        #pragma unroll
        for (int hp = 0; hp < 8; hp++) {
            ull pv = pp[hp];
            #pragma unroll
            for (int ii = 0; ii < 4; ii++)
                acc[ii][hp] = f2fma(pv, zz[ii], acc[ii][hp]);
        }
    }

    float* dst = g_ctxp + (size_t)ns * (B * H * D) + (size_t)b * H * D;
    #pragma unroll
    for (int hp = 0; hp < 8; hp++)
        #pragma unroll
        for (int ii = 0; ii < 4; ii++) {
            float2 v = unpack2(acc[ii][hp]);
            dst[(size_t)(2 * hp) * D + i0 + ii]     = v.x;
            dst[(size_t)(2 * hp + 1) * D + i0 + ii] = v.y;
        }
}

// ---------------- K5b: reduce the NSPLIT partials (deterministic, pure BW) ---
__global__ void k_ctxred() {
    int x = blockIdx.x * 256 + threadIdx.x;     // float4 index, 131072 total
    const float4* src = reinterpret_cast<const float4*>(g_ctxp);
    float4 a = src[x];
    #pragma unroll
    for (int ns = 1; ns < NSPLIT; ns++) {
        float4 v = src[(size_t)ns * (B * H * D / 4) + x];
        a.x += v.x; a.y += v.y; a.z += v.z; a.w += v.w;
    }
    reinterpret_cast<float4*>(g_ctx)[x] = a;
}

// ---------------- K6: pooled = w_v . ctx + b_v  (4-way batch-split) ----------
__global__ void k_pooled(const float* __restrict__ w_v, const float* __restrict__ b_v) {
    __shared__ float ws[8 * D];
    int jt = blockIdx.x >> 2;        // 0..127 j-tile
    int bg = blockIdx.x & 3;         // 0..3 batch group (8 batches)
    int j0 = jt * 8;
    for (int idx = threadIdx.x; idx < 8 * D; idx += 256)
        ws[idx] = w_v[(size_t)j0 * D + idx];
    __syncthreads();

    int w = threadIdx.x >> 5, lane = threadIdx.x & 31;
    int j = j0 + w;
    int h = j >> 6;
    float bias = b_v[j];
    const float4* wr = reinterpret_cast<const float4*>(ws + w * D);
    for (int bb = 0; bb < 8; bb++) {
        int b = bg * 8 + bb;
        const float4* cx = reinterpret_cast<const float4*>(g_ctx + ((size_t)(b * H + h)) * D);
        float acc = 0.f;
        #pragma unroll
        for (int i4 = lane; i4 < D / 4; i4 += 32) {
            float4 a = wr[i4];
            float4 c = __ldg(&cx[i4]);
            acc = fmaf(a.x, c.x, acc);
            acc = fmaf(a.y, c.y, acc);
            acc = fmaf(a.z, c.z, acc);
            acc = fmaf(a.w, c.w, acc);
        }
        acc = warp_sum(acc);
        if (lane == 0) g_pooled[b * D + j] = acc + bias;
    }
}

// ---------------- K7: out = w_o . pooled + b_o  (4-way batch-split) ----------
__global__ void k_out(const float* __restrict__ w_o, const float* __restrict__ b_o,
                      float* __restrict__ out) {
    __shared__ float ws[8 * D];
    int jt = blockIdx.x >> 2;
    int bg = blockIdx.x & 3;
    int j0 = jt * 8;
    for (int idx = threadIdx.x; idx < 8 * D; idx += 256)
        ws[idx] = w_o[(size_t)j0 * D + idx];
    __syncthreads();

    int w = threadIdx.x >> 5, lane = threadIdx.x & 31;
    int j = j0 + w;
    float bias = b_o[j];
    const float4* wr = reinterpret_cast<const float4*>(ws + w * D);
    for (int bb = 0; bb < 8; bb++) {
        int b = bg * 8 + bb;
        const float4* px = reinterpret_cast<const float4*>(g_pooled + (size_t)b * D);
        float acc = 0.f;
        #pragma unroll
        for (int i4 = lane; i4 < D / 4; i4 += 32) {
            float4 a = wr[i4];
            float4 c = __ldg(&px[i4]);
            acc = fmaf(a.x, c.x, acc);
            acc = fmaf(a.y, c.y, acc);
            acc = fmaf(a.z, c.z, acc);
            acc = fmaf(a.w, c.w, acc);
        }
        acc = warp_sum(acc);
        if (lane == 0) out[b * D + j] = acc + bias;
    }
}

// ---------------- launch ------------------------------------------------------
extern "C" void kernel_launch(void* const* d_in, const int* in_sizes, int n_in,
                              void* d_out, int out_size) {
    const float* z     = (const float*)d_in[0];
    const void*  mask  = d_in[1];
    const float* query = (const float*)d_in[2];
    const float* w_q   = (const float*)d_in[3];
    const float* w_k   = (const float*)d_in[4];
    const float* w_v   = (const float*)d_in[5];
    const float* b_q   = (const float*)d_in[6];
    const float* b_k   = (const float*)d_in[7];
    const float* b_v   = (const float*)d_in[8];
    const float* w_o   = (const float*)d_in[9];
    const float* b_o   = (const float*)d_in[10];
    float*       out   = (float*)d_out;

    // u smem (1024*18) + softmax partials (2*16*32) = 77824 B
    cudaFuncSetAttribute(k_scores, cudaFuncAttributeMaxDynamicSharedMemorySize, 77824);

    kA       <<<160, 256>>>(query, w_q, b_q, mask);
    kB       <<<65, 256>>>(w_k, b_k);
    k_scores <<<(B * N) / 128, 256, 77824>>>(z);
    k_ctx    <<<B * NSPLIT, 256>>>(z);
    k_ctxred <<<(B * H * D / 4) / 256, 256>>>();
    k_pooled <<<512, 256>>>(w_v, b_v);
    k_out    <<<512, 256>>>(w_o, b_o, out);
}